// round 3
// baseline (speedup 1.0000x reference)
#include <cuda_runtime.h>
#include <cstdint>

#define B 32
#define D 128
#define DIN 2048
#define A 7
#define K 5
#define TR 128          // reps rows per tile
#define GBLK 296        // 2 blocks per SM, one wave
#define KSPLIT 16
#define KSLICE (DIN / KSPLIT)   // 128

// ---------------- scratch (no allocations allowed) ----------------
__device__ float g_partial[KSPLIT * B * D];
__device__ float g_brep[B * D];
__device__ float g_anorm[B];
__device__ float g_cand_d[GBLK * B * K];
__device__ int   g_cand_i[GBLK * B * K];

// ---------------- top-5 register insert (ascending, d0 best) ----------------
__device__ __forceinline__ void top5_insert(float sq, int idx,
    float& d0, float& d1, float& d2, float& d3, float& d4,
    int& j0, int& j1, int& j2, int& j3, int& j4)
{
    if (sq >= d4) return;
    if (sq < d2) {
        d4 = d3; j4 = j3; d3 = d2; j3 = j2;
        if (sq < d1) {
            d2 = d1; j2 = j1;
            if (sq < d0) { d1 = d0; j1 = j0; d0 = sq; j0 = idx; }
            else         { d1 = sq; j1 = idx; }
        } else { d2 = sq; j2 = idx; }
    } else {
        if (sq < d3) { d4 = d3; j4 = j3; d3 = sq; j3 = idx; }
        else         { d4 = sq; j4 = idx; }
    }
}

// ---------------- kernel 1: encoder split-K partial GEMM ----------------
// grid (KSPLIT, B), 128 threads. thread d computes partial dot over its K slice.
__global__ void enc_partial_kernel(const float* __restrict__ x,
                                   const float* __restrict__ W)
{
    const int ks = blockIdx.x;
    const int b  = blockIdx.y;
    const int d  = threadIdx.x;
    __shared__ float xs[KSLICE];
    xs[d] = x[b * DIN + ks * KSLICE + d];
    __syncthreads();
    const float* Wp = W + (size_t)(ks * KSLICE) * D + d;
    float acc = 0.f;
#pragma unroll 8
    for (int i = 0; i < KSLICE; i++)
        acc = fmaf(xs[i], Wp[(size_t)i * D], acc);
    g_partial[(ks * B + b) * D + d] = acc;
}

// ---------------- kernel 1b: reduce partials, add bias, compute |a|^2 ----------------
__global__ void enc_reduce_kernel(const float* __restrict__ b_enc)
{
    const int b = blockIdx.x;
    const int d = threadIdx.x;
    float r = b_enc[d];
#pragma unroll
    for (int ks = 0; ks < KSPLIT; ks++)
        r += g_partial[(ks * B + b) * D + d];
    g_brep[b * D + d] = r;

    float s = r * r;
#pragma unroll
    for (int o = 16; o; o >>= 1) s += __shfl_xor_sync(0xffffffffu, s, o);
    __shared__ float ws[4];
    if ((d & 31) == 0) ws[d >> 5] = s;
    __syncthreads();
    if (d == 0) g_anorm[b] = ws[0] + ws[1] + ws[2] + ws[3];
}

// ---------------- kernel 2: fused cdist + per-block top-5 ----------------
// 256 threads (8 warps). lane == batch. Each warp handles 16 rows/tile, 4 rows at a time.
// smem: a_s[32][132] | rep_s[128][132] | rn_s[128]  (132-pad -> conflict-free LDS.128)
__global__ void __launch_bounds__(256, 2) dist_topk_kernel(
    const float* __restrict__ reps, int N)
{
    extern __shared__ float sm[];
    float* a_s   = sm;                         // 32*132 = 4224 floats
    float* rep_s = sm + 32 * 132;              // 128*132 = 16896 floats
    float* rn_s  = sm + 32 * 132 + 128 * 132;  // 128 floats

    const int tid  = threadIdx.x;
    const int lane = tid & 31;
    const int w    = tid >> 5;

    // stage batch reps: g_brep[32][128] -> a_s[b][132] (float4 index b*33+c)
    for (int i = tid; i < 32 * 32; i += 256) {
        const int b = i >> 5, c = i & 31;
        ((float4*)a_s)[b * 33 + c] = ((const float4*)g_brep)[i];
    }
    const float an = g_anorm[lane];

    float d0 = 3.4e38f, d1 = 3.4e38f, d2 = 3.4e38f, d3 = 3.4e38f, d4 = 3.4e38f;
    int   j0 = 0, j1 = 0, j2 = 0, j3 = 0, j4 = 0;

    const int ntiles = (N + TR - 1) / TR;
    for (int t = blockIdx.x; t < ntiles; t += GBLK) {
        const int row0 = t * TR;
        __syncthreads();   // previous tile fully consumed before overwrite

        // ---- load tile: warp w loads rows w, w+8, ... (coalesced 512B/warp) ----
#pragma unroll
        for (int it = 0; it < 16; it++) {
            const int r  = it * 8 + w;
            const int gr = row0 + r;
            float4 v = make_float4(0.f, 0.f, 0.f, 0.f);
            const bool valid = (gr < N);
            if (valid) v = __ldg((const float4*)reps + (size_t)gr * 32 + lane);
            ((float4*)rep_s)[r * 33 + lane] = v;
            float s = v.x * v.x + v.y * v.y + v.z * v.z + v.w * v.w;
#pragma unroll
            for (int o = 16; o; o >>= 1) s += __shfl_xor_sync(0xffffffffu, s, o);
            if (lane == 0) rn_s[r] = valid ? s : 3.0e38f;
        }
        __syncthreads();

        // ---- compute: warp w owns local rows [w*16, w*16+16), 4 rows per pass ----
#pragma unroll
        for (int it = 0; it < 4; it++) {
            const int rb = w * 16 + it * 4;
            const float4* ap  = (const float4*)a_s + lane * 33;
            const float4* q0p = (const float4*)rep_s + (rb + 0) * 33;
            const float4* q1p = q0p + 33;
            const float4* q2p = q0p + 66;
            const float4* q3p = q0p + 99;
            float acc0 = 0.f, acc1 = 0.f, acc2 = 0.f, acc3 = 0.f;
#pragma unroll 8
            for (int k = 0; k < 32; k++) {
                const float4 a  = ap[k];
                const float4 q0 = q0p[k];
                const float4 q1 = q1p[k];
                const float4 q2 = q2p[k];
                const float4 q3 = q3p[k];
                acc0 = fmaf(a.x, q0.x, acc0); acc0 = fmaf(a.y, q0.y, acc0);
                acc0 = fmaf(a.z, q0.z, acc0); acc0 = fmaf(a.w, q0.w, acc0);
                acc1 = fmaf(a.x, q1.x, acc1); acc1 = fmaf(a.y, q1.y, acc1);
                acc1 = fmaf(a.z, q1.z, acc1); acc1 = fmaf(a.w, q1.w, acc1);
                acc2 = fmaf(a.x, q2.x, acc2); acc2 = fmaf(a.y, q2.y, acc2);
                acc2 = fmaf(a.z, q2.z, acc2); acc2 = fmaf(a.w, q2.w, acc2);
                acc3 = fmaf(a.x, q3.x, acc3); acc3 = fmaf(a.y, q3.y, acc3);
                acc3 = fmaf(a.z, q3.z, acc3); acc3 = fmaf(a.w, q3.w, acc3);
            }
            const int grow = row0 + rb;
            float sq;
            sq = an + rn_s[rb + 0] - 2.f * acc0;
            top5_insert(sq, grow + 0, d0, d1, d2, d3, d4, j0, j1, j2, j3, j4);
            sq = an + rn_s[rb + 1] - 2.f * acc1;
            top5_insert(sq, grow + 1, d0, d1, d2, d3, d4, j0, j1, j2, j3, j4);
            sq = an + rn_s[rb + 2] - 2.f * acc2;
            top5_insert(sq, grow + 2, d0, d1, d2, d3, d4, j0, j1, j2, j3, j4);
            sq = an + rn_s[rb + 3] - 2.f * acc3;
            top5_insert(sq, grow + 3, d0, d1, d2, d3, d4, j0, j1, j2, j3, j4);
        }
    }

    // ---- block merge: 8 warp-lists of 5 per batch -> 5 ----
    __syncthreads();
    float* md = rep_s;                       // [8][32][5] floats
    int*   mi = (int*)(rep_s + 8 * 32 * 5);  // [8][32][5] ints
    const int base = (w * 32 + lane) * 5;
    md[base + 0] = d0; md[base + 1] = d1; md[base + 2] = d2; md[base + 3] = d3; md[base + 4] = d4;
    mi[base + 0] = j0; mi[base + 1] = j1; mi[base + 2] = j2; mi[base + 3] = j3; mi[base + 4] = j4;
    __syncthreads();
    if (tid < 32) {
        float e0 = 3.4e38f, e1 = 3.4e38f, e2 = 3.4e38f, e3 = 3.4e38f, e4 = 3.4e38f;
        int   m0 = 0, m1 = 0, m2 = 0, m3 = 0, m4 = 0;
        for (int ww = 0; ww < 8; ww++) {
            const int bb = (ww * 32 + tid) * 5;
#pragma unroll
            for (int j = 0; j < 5; j++)
                top5_insert(md[bb + j], mi[bb + j], e0, e1, e2, e3, e4, m0, m1, m2, m3, m4);
        }
        const int ob = (blockIdx.x * 32 + tid) * 5;
        g_cand_d[ob + 0] = e0; g_cand_d[ob + 1] = e1; g_cand_d[ob + 2] = e2;
        g_cand_d[ob + 3] = e3; g_cand_d[ob + 4] = e4;
        g_cand_i[ob + 0] = m0; g_cand_i[ob + 1] = m1; g_cand_i[ob + 2] = m2;
        g_cand_i[ob + 3] = m3; g_cand_i[ob + 4] = m4;
    }
}

// ---------------- kernel 3: global merge + softmax + action gather ----------------
__global__ void finalize_kernel(const float* __restrict__ actions,
                                float* __restrict__ out)
{
    const int b   = blockIdx.x;
    const int tid = threadIdx.x;

    float d0 = 3.4e38f, d1 = 3.4e38f, d2 = 3.4e38f, d3 = 3.4e38f, d4 = 3.4e38f;
    int   j0 = 0, j1 = 0, j2 = 0, j3 = 0, j4 = 0;
    const int total = GBLK * K;
    for (int c = tid; c < total; c += 128) {
        const int g = c / K, j = c - g * K;
        const int idx = (g * B + b) * K + j;
        top5_insert(g_cand_d[idx], g_cand_i[idx], d0, d1, d2, d3, d4, j0, j1, j2, j3, j4);
    }

    __shared__ float sd[128 * 5];
    __shared__ int   si[128 * 5];
    sd[tid * 5 + 0] = d0; sd[tid * 5 + 1] = d1; sd[tid * 5 + 2] = d2;
    sd[tid * 5 + 3] = d3; sd[tid * 5 + 4] = d4;
    si[tid * 5 + 0] = j0; si[tid * 5 + 1] = j1; si[tid * 5 + 2] = j2;
    si[tid * 5 + 3] = j3; si[tid * 5 + 4] = j4;
    __syncthreads();

    __shared__ float sd2[32 * 5];
    __shared__ int   si2[32 * 5];
    if (tid < 32) {
        float e0 = 3.4e38f, e1 = 3.4e38f, e2 = 3.4e38f, e3 = 3.4e38f, e4 = 3.4e38f;
        int   m0 = 0, m1 = 0, m2 = 0, m3 = 0, m4 = 0;
        for (int q = 0; q < 4; q++) {
            const int bb = (tid * 4 + q) * 5;
#pragma unroll
            for (int j = 0; j < 5; j++)
                top5_insert(sd[bb + j], si[bb + j], e0, e1, e2, e3, e4, m0, m1, m2, m3, m4);
        }
        sd2[tid * 5 + 0] = e0; sd2[tid * 5 + 1] = e1; sd2[tid * 5 + 2] = e2;
        sd2[tid * 5 + 3] = e3; sd2[tid * 5 + 4] = e4;
        si2[tid * 5 + 0] = m0; si2[tid * 5 + 1] = m1; si2[tid * 5 + 2] = m2;
        si2[tid * 5 + 3] = m3; si2[tid * 5 + 4] = m4;
    }
    __syncthreads();

    if (tid == 0) {
        float e0 = 3.4e38f, e1 = 3.4e38f, e2 = 3.4e38f, e3 = 3.4e38f, e4 = 3.4e38f;
        int   m0 = 0, m1 = 0, m2 = 0, m3 = 0, m4 = 0;
        for (int q = 0; q < 32; q++) {
            const int bb = q * 5;
#pragma unroll
            for (int j = 0; j < 5; j++)
                top5_insert(sd2[bb + j], si2[bb + j], e0, e1, e2, e3, e4, m0, m1, m2, m3, m4);
        }
        const float t0 = sqrtf(fmaxf(e0, 1e-12f));
        const float t1 = sqrtf(fmaxf(e1, 1e-12f));
        const float t2 = sqrtf(fmaxf(e2, 1e-12f));
        const float t3 = sqrtf(fmaxf(e3, 1e-12f));
        const float t4 = sqrtf(fmaxf(e4, 1e-12f));
        const float dmin = t0;   // e0 is the smallest (sorted), sqrt monotone
        const float w0 = expf(dmin - t0);
        const float w1 = expf(dmin - t1);
        const float w2 = expf(dmin - t2);
        const float w3 = expf(dmin - t3);
        const float w4 = expf(dmin - t4);
        const float inv = 1.f / (w0 + w1 + w2 + w3 + w4);
        const float* a0 = actions + (size_t)m0 * A;
        const float* a1 = actions + (size_t)m1 * A;
        const float* a2 = actions + (size_t)m2 * A;
        const float* a3 = actions + (size_t)m3 * A;
        const float* a4 = actions + (size_t)m4 * A;
#pragma unroll
        for (int a = 0; a < A; a++) {
            out[b * A + a] = (w0 * a0[a] + w1 * a1[a] + w2 * a2[a] +
                              w3 * a3[a] + w4 * a4[a]) * inv;
        }
    }
}

// ---------------- launch ----------------
extern "C" void kernel_launch(void* const* d_in, const int* in_sizes, int n_in,
                              void* d_out, int out_size)
{
    const float* x       = (const float*)d_in[0];
    const float* W       = (const float*)d_in[1];
    const float* b_enc   = (const float*)d_in[2];
    const float* reps    = (const float*)d_in[3];
    const float* actions = (const float*)d_in[4];
    const int N = in_sizes[3] / D;

    constexpr int SMEM2 = (32 * 132 + 128 * 132 + 128) * (int)sizeof(float); // 84992B
    cudaFuncSetAttribute(dist_topk_kernel,
                         cudaFuncAttributeMaxDynamicSharedMemorySize, SMEM2);

    enc_partial_kernel<<<dim3(KSPLIT, B), 128>>>(x, W);
    enc_reduce_kernel<<<B, 128>>>(b_enc);
    dist_topk_kernel<<<GBLK, 256, SMEM2>>>(reps, N);
    finalize_kernel<<<B, 128>>>(actions, (float*)d_out);
}

// round 4
// speedup vs baseline: 1.0352x; 1.0352x over previous
#include <cuda_runtime.h>
#include <cstdint>

#define B 32
#define D 128
#define DIN 2048
#define A 7
#define K 5
#define TR 128           // reps rows per tile
#define GBLK 148         // 1 CTA per SM, one wave
#define PITCH 33         // ulonglong2 (16B) per tile row = 132 floats
#define KSPLIT 16
#define KSLICE (DIN / KSPLIT)   // 128

typedef unsigned long long ull;

// ---------------- scratch (no allocations allowed) ----------------
__device__ float g_partial[KSPLIT * B * D];
__device__ float g_brep[B * D];
__device__ float g_anorm[B];
__device__ float g_cand_d[B * GBLK * K];   // [batch][block][5]  (coalesced for finalize)
__device__ int   g_cand_i[B * GBLK * K];

// ---------------- f32x2 helpers (double-rate fp32 path) ----------------
__device__ __forceinline__ void ffma2(ull& d, const ull a, const ull b) {
    asm("fma.rn.f32x2 %0, %1, %2, %0;" : "+l"(d) : "l"(a), "l"(b));
}
__device__ __forceinline__ float2 unpack2(ull v) {
    float2 r;
    asm("mov.b64 {%0, %1}, %2;" : "=f"(r.x), "=f"(r.y) : "l"(v));
    return r;
}

// ---------------- NaN-safe top-5 register insert (ascending, d0 best) ----------------
__device__ __forceinline__ void top5_insert(float sq, int idx,
    float& d0, float& d1, float& d2, float& d3, float& d4,
    int& j0, int& j1, int& j2, int& j3, int& j4)
{
    if (!(sq < d4)) return;           // NaN-safe: NaN fails and exits
    if (sq < d2) {
        d4 = d3; j4 = j3; d3 = d2; j3 = j2;
        if (sq < d1) {
            d2 = d1; j2 = j1;
            if (sq < d0) { d1 = d0; j1 = j0; d0 = sq; j0 = idx; }
            else         { d1 = sq; j1 = idx; }
        } else { d2 = sq; j2 = idx; }
    } else {
        if (sq < d3) { d4 = d3; j4 = j3; d3 = sq; j3 = idx; }
        else         { d4 = sq; j4 = idx; }
    }
}

// ---------------- kernel 1: encoder split-K partial GEMM ----------------
__global__ void enc_partial_kernel(const float* __restrict__ x,
                                   const float* __restrict__ W)
{
    const int ks = blockIdx.x;
    const int b  = blockIdx.y;
    const int d  = threadIdx.x;
    __shared__ float xs[KSLICE];
    xs[d] = x[b * DIN + ks * KSLICE + d];
    __syncthreads();
    const float* Wp = W + (size_t)(ks * KSLICE) * D + d;
    float acc = 0.f;
#pragma unroll 8
    for (int i = 0; i < KSLICE; i++)
        acc = fmaf(xs[i], Wp[(size_t)i * D], acc);
    g_partial[(ks * B + b) * D + d] = acc;
}

// ---------------- kernel 1b: reduce partials, add bias, compute |a|^2 ----------------
__global__ void enc_reduce_kernel(const float* __restrict__ b_enc)
{
    const int b = blockIdx.x;
    const int d = threadIdx.x;
    float r = b_enc[d];
#pragma unroll
    for (int ks = 0; ks < KSPLIT; ks++)
        r += g_partial[(ks * B + b) * D + d];
    g_brep[b * D + d] = r;

    float s = r * r;
#pragma unroll
    for (int o = 16; o; o >>= 1) s += __shfl_xor_sync(0xffffffffu, s, o);
    __shared__ float ws[4];
    if ((d & 31) == 0) ws[d >> 5] = s;
    __syncthreads();
    if (d == 0) g_anorm[b] = ws[0] + ws[1] + ws[2] + ws[3];
}

// ---------------- cp.async tile load: 256 threads, 128 rows x 128 floats ----------------
__device__ __forceinline__ void load_tile_async(ulonglong2* buf,
                                                const float* __restrict__ reps,
                                                int row0, int N, int tid)
{
#pragma unroll
    for (int j = 0; j < 16; j++) {
        const int c   = tid + j * 256;     // 0..4095
        const int row = c >> 5;
        const int col = c & 31;            // float4 column
        const int gr  = row0 + row;
        if (gr < N) {
            const float4* src = (const float4*)reps + (size_t)gr * 32 + col;
            unsigned dst = (unsigned)__cvta_generic_to_shared(buf + row * PITCH + col);
            asm volatile("cp.async.cg.shared.global [%0], [%1], 16;"
                         :: "r"(dst), "l"(src) : "memory");
        }
    }
}

// ---------------- kernel 2: fused cdist (f32x2) + per-block top-5 ----------------
// 256 threads (8 warps). lane == batch (a vector held in 128 registers/lane).
// Double-buffered cp.async tile pipeline; q rows read as broadcast LDS.128.
__global__ void __launch_bounds__(256) dist_topk_kernel(
    const float* __restrict__ reps, int N)
{
    extern __shared__ char smraw[];
    ulonglong2* buf0 = (ulonglong2*)smraw;                 // 128*33 u2 = 67584 B
    ulonglong2* buf1 = buf0 + 128 * PITCH;                 // 67584 B
    float* rn0 = (float*)(buf1 + 128 * PITCH);             // 128 floats
    float* rn1 = rn0 + 128;

    const int tid  = threadIdx.x;
    const int lane = tid & 31;
    const int w    = tid >> 5;

    // batch vector of this lane -> registers (64 x b64 = 128 regs, loop-invariant)
    ull a2[64];
    {
        const ulonglong2* ap = (const ulonglong2*)g_brep + lane * 32;
#pragma unroll
        for (int i = 0; i < 32; i++) {
            ulonglong2 v = ap[i];
            a2[2 * i] = v.x; a2[2 * i + 1] = v.y;
        }
    }
    const float an = g_anorm[lane];

    float d0 = 3.4e38f, d1 = 3.4e38f, d2 = 3.4e38f, d3 = 3.4e38f, d4 = 3.4e38f;
    int   j0 = 0, j1 = 0, j2 = 0, j3 = 0, j4 = 0;

    const int ntiles = (N + TR - 1) / TR;

    // prologue: async-load first tile
    if (blockIdx.x < ntiles)
        load_tile_async(buf0, reps, blockIdx.x * TR, N, tid);
    asm volatile("cp.async.commit_group;" ::: "memory");

    int i = 0;
    for (int t = blockIdx.x; t < ntiles; t += GBLK, ++i) {
        ulonglong2* cur = (i & 1) ? buf1 : buf0;
        ulonglong2* nxt = (i & 1) ? buf0 : buf1;
        float*      rnc = (i & 1) ? rn1  : rn0;

        // prefetch next tile (nxt buffer was fully consumed before last end-sync)
        const int tn = t + GBLK;
        if (tn < ntiles)
            load_tile_async(nxt, reps, tn * TR, N, tid);
        asm volatile("cp.async.commit_group;" ::: "memory");
        asm volatile("cp.async.wait_group 1;" ::: "memory");   // cur is ready
        __syncthreads();

        // ---- row-norm pass: 2 threads per row ----
        {
            const int row  = tid >> 1;
            const int half = tid & 1;
            const int gr   = t * TR + row;
            const ulonglong2* rp = cur + row * PITCH + half * 16;
            ull nacc = 0;
#pragma unroll
            for (int kk = 0; kk < 16; kk++) {
                ulonglong2 v = rp[kk];
                ffma2(nacc, v.x, v.x);
                ffma2(nacc, v.y, v.y);
            }
            float2 nf = unpack2(nacc);
            float s = nf.x + nf.y;
            s += __shfl_xor_sync(0xffffffffu, s, 1);
            if (half == 0) rnc[row] = (gr < N) ? s : 3.4e38f;
        }
        __syncthreads();

        // ---- compute: warp w owns rows [w*16, w*16+16), 4 rows per pass ----
#pragma unroll 1
        for (int pass = 0; pass < 4; pass++) {
            const int rb = w * 16 + pass * 4;
            const ulonglong2* q0 = cur + (rb + 0) * PITCH;
            const ulonglong2* q1 = q0 + PITCH;
            const ulonglong2* q2 = q0 + 2 * PITCH;
            const ulonglong2* q3 = q0 + 3 * PITCH;
            ull acc0 = 0, acc1 = 0, acc2 = 0, acc3 = 0;
#pragma unroll
            for (int k = 0; k < 32; k++) {
                const ulonglong2 v0 = q0[k];
                const ulonglong2 v1 = q1[k];
                const ulonglong2 v2 = q2[k];
                const ulonglong2 v3 = q3[k];
                ffma2(acc0, a2[2 * k], v0.x); ffma2(acc0, a2[2 * k + 1], v0.y);
                ffma2(acc1, a2[2 * k], v1.x); ffma2(acc1, a2[2 * k + 1], v1.y);
                ffma2(acc2, a2[2 * k], v2.x); ffma2(acc2, a2[2 * k + 1], v2.y);
                ffma2(acc3, a2[2 * k], v3.x); ffma2(acc3, a2[2 * k + 1], v3.y);
            }
            const int grow = t * TR + rb;
            float2 f;
            f = unpack2(acc0);
            top5_insert(an + rnc[rb + 0] - 2.f * (f.x + f.y), grow + 0,
                        d0, d1, d2, d3, d4, j0, j1, j2, j3, j4);
            f = unpack2(acc1);
            top5_insert(an + rnc[rb + 1] - 2.f * (f.x + f.y), grow + 1,
                        d0, d1, d2, d3, d4, j0, j1, j2, j3, j4);
            f = unpack2(acc2);
            top5_insert(an + rnc[rb + 2] - 2.f * (f.x + f.y), grow + 2,
                        d0, d1, d2, d3, d4, j0, j1, j2, j3, j4);
            f = unpack2(acc3);
            top5_insert(an + rnc[rb + 3] - 2.f * (f.x + f.y), grow + 3,
                        d0, d1, d2, d3, d4, j0, j1, j2, j3, j4);
        }
        __syncthreads();   // tile fully consumed; its buffer may be refilled next iter
    }

    // ---- block merge: 8 warp-lists of 5 per batch -> 5 ----
    float* md = (float*)buf0;                 // [8][32][5] floats
    int*   mi = (int*)(md + 8 * 32 * 5);      // [8][32][5] ints
    const int base = (w * 32 + lane) * 5;
    md[base + 0] = d0; md[base + 1] = d1; md[base + 2] = d2; md[base + 3] = d3; md[base + 4] = d4;
    mi[base + 0] = j0; mi[base + 1] = j1; mi[base + 2] = j2; mi[base + 3] = j3; mi[base + 4] = j4;
    __syncthreads();
    if (tid < 32) {
        float e0 = 3.4e38f, e1 = 3.4e38f, e2 = 3.4e38f, e3 = 3.4e38f, e4 = 3.4e38f;
        int   m0 = 0, m1 = 0, m2 = 0, m3 = 0, m4 = 0;
        for (int ww = 0; ww < 8; ww++) {
            const int bb = (ww * 32 + tid) * 5;
#pragma unroll
            for (int j = 0; j < 5; j++)
                top5_insert(md[bb + j], mi[bb + j], e0, e1, e2, e3, e4, m0, m1, m2, m3, m4);
        }
        // layout: [batch][block][5] -> finalize reads contiguously per batch
        const int ob = (tid * GBLK + blockIdx.x) * K;
        g_cand_d[ob + 0] = e0; g_cand_d[ob + 1] = e1; g_cand_d[ob + 2] = e2;
        g_cand_d[ob + 3] = e3; g_cand_d[ob + 4] = e4;
        g_cand_i[ob + 0] = m0; g_cand_i[ob + 1] = m1; g_cand_i[ob + 2] = m2;
        g_cand_i[ob + 3] = m3; g_cand_i[ob + 4] = m4;
    }
}

// ---------------- kernel 3: global merge + softmax + action gather ----------------
__global__ void finalize_kernel(const float* __restrict__ actions,
                                float* __restrict__ out)
{
    const int b   = blockIdx.x;
    const int tid = threadIdx.x;   // 256 threads

    const float* cd = g_cand_d + (size_t)b * GBLK * K;   // contiguous 740 floats
    const int*   ci = g_cand_i + (size_t)b * GBLK * K;

    float d0 = 3.4e38f, d1 = 3.4e38f, d2 = 3.4e38f, d3 = 3.4e38f, d4 = 3.4e38f;
    int   j0 = 0, j1 = 0, j2 = 0, j3 = 0, j4 = 0;
    for (int c = tid; c < GBLK * K; c += 256)
        top5_insert(cd[c], ci[c], d0, d1, d2, d3, d4, j0, j1, j2, j3, j4);

    __shared__ float sd[256 * 5];
    __shared__ int   si[256 * 5];
    sd[tid * 5 + 0] = d0; sd[tid * 5 + 1] = d1; sd[tid * 5 + 2] = d2;
    sd[tid * 5 + 3] = d3; sd[tid * 5 + 4] = d4;
    si[tid * 5 + 0] = j0; si[tid * 5 + 1] = j1; si[tid * 5 + 2] = j2;
    si[tid * 5 + 3] = j3; si[tid * 5 + 4] = j4;
    __syncthreads();

    __shared__ float sd2[32 * 5];
    __shared__ int   si2[32 * 5];
    if (tid < 32) {
        float e0 = 3.4e38f, e1 = 3.4e38f, e2 = 3.4e38f, e3 = 3.4e38f, e4 = 3.4e38f;
        int   m0 = 0, m1 = 0, m2 = 0, m3 = 0, m4 = 0;
        for (int q = 0; q < 8; q++) {
            const int bb = (tid * 8 + q) * 5;
#pragma unroll
            for (int j = 0; j < 5; j++)
                top5_insert(sd[bb + j], si[bb + j], e0, e1, e2, e3, e4, m0, m1, m2, m3, m4);
        }
        sd2[tid * 5 + 0] = e0; sd2[tid * 5 + 1] = e1; sd2[tid * 5 + 2] = e2;
        sd2[tid * 5 + 3] = e3; sd2[tid * 5 + 4] = e4;
        si2[tid * 5 + 0] = m0; si2[tid * 5 + 1] = m1; si2[tid * 5 + 2] = m2;
        si2[tid * 5 + 3] = m3; si2[tid * 5 + 4] = m4;
    }
    __syncthreads();

    if (tid == 0) {
        float e0 = 3.4e38f, e1 = 3.4e38f, e2 = 3.4e38f, e3 = 3.4e38f, e4 = 3.4e38f;
        int   m0 = 0, m1 = 0, m2 = 0, m3 = 0, m4 = 0;
        for (int q = 0; q < 32; q++) {
            const int bb = q * 5;
#pragma unroll
            for (int j = 0; j < 5; j++)
                top5_insert(sd2[bb + j], si2[bb + j], e0, e1, e2, e3, e4, m0, m1, m2, m3, m4);
        }
        const float t0 = sqrtf(fmaxf(e0, 1e-12f));
        const float t1 = sqrtf(fmaxf(e1, 1e-12f));
        const float t2 = sqrtf(fmaxf(e2, 1e-12f));
        const float t3 = sqrtf(fmaxf(e3, 1e-12f));
        const float t4 = sqrtf(fmaxf(e4, 1e-12f));
        const float dmin = t0;   // ascending order, sqrt monotone
        const float w0 = expf(dmin - t0);
        const float w1 = expf(dmin - t1);
        const float w2 = expf(dmin - t2);
        const float w3 = expf(dmin - t3);
        const float w4 = expf(dmin - t4);
        const float inv = 1.f / (w0 + w1 + w2 + w3 + w4);
        const float* a0 = actions + (size_t)m0 * A;
        const float* a1 = actions + (size_t)m1 * A;
        const float* a2p = actions + (size_t)m2 * A;
        const float* a3 = actions + (size_t)m3 * A;
        const float* a4 = actions + (size_t)m4 * A;
#pragma unroll
        for (int a = 0; a < A; a++) {
            out[b * A + a] = (w0 * a0[a] + w1 * a1[a] + w2 * a2p[a] +
                              w3 * a3[a] + w4 * a4[a]) * inv;
        }
    }
}

// ---------------- launch ----------------
extern "C" void kernel_launch(void* const* d_in, const int* in_sizes, int n_in,
                              void* d_out, int out_size)
{
    const float* x       = (const float*)d_in[0];
    const float* W       = (const float*)d_in[1];
    const float* b_enc   = (const float*)d_in[2];
    const float* reps    = (const float*)d_in[3];
    const float* actions = (const float*)d_in[4];
    const int N = in_sizes[3] / D;

    constexpr int SMEM2 = 2 * 128 * PITCH * 16 + 2 * 128 * 4;   // 136192 B
    static int attr_done = 0;
    if (!attr_done) {
        cudaFuncSetAttribute(dist_topk_kernel,
                             cudaFuncAttributeMaxDynamicSharedMemorySize, SMEM2);
        attr_done = 1;
    }

    enc_partial_kernel<<<dim3(KSPLIT, B), 128>>>(x, W);
    enc_reduce_kernel<<<B, 128>>>(b_enc);
    dist_topk_kernel<<<GBLK, 256, SMEM2>>>(reps, N);
    finalize_kernel<<<B, 256>>>(actions, (float*)d_out);
}